// round 8
// baseline (speedup 1.0000x reference)
#include <cuda_runtime.h>
#include <cuda_bf16.h>
#include <math.h>
#include <stdint.h>

#define N_NODES 100000
#define N_EDGES 1200000
#define CH 64
#define SCAN_B 1024
#define NB ((N_NODES + SCAN_B - 1) / SCAN_B)   // 98 blocks

// ---------------- scratch (static device memory; no allocs allowed) ----------
__device__ float g_xin [N_NODES * CH];
__device__ float g_h1  [N_NODES * CH];
__device__ int   g_deg [N_NODES];        // zeroed at load; scan re-zeroes after use
__device__ int   g_rowstart[N_NODES + 1];
__device__ int   g_fill[N_NODES];
__device__ int   g_src_sorted[N_EDGES];
__device__ int   g_blk_stat[NB];         // 0 pending, 1 agg ready, 2 incl ready; fill resets
__device__ int   g_blk_agg[NB];
__device__ int   g_blk_inc[NB];

// ---------------- per-block edge dtype detection (warp ballot) ---------------
// int64 little-endian with values < 2^31 => all odd 32-bit words of the first
// 64 entries are zero. Each block computes this locally (cheap L2 hits).
__device__ __forceinline__ int detect_is64_block(const void* ei, int* s_flag) {
    int tid = threadIdx.x;
    if (tid < 32) {
        const int* w = (const int*)ei;
        int ok = (w[2 * tid + 1] == 0) && (w[2 * (tid + 32) + 1] == 0);
        unsigned m = __ballot_sync(0xffffffffu, ok);
        if (tid == 0) *s_flag = (m == 0xffffffffu);
    }
    __syncthreads();
    return *s_flag;
}

__device__ __forceinline__ int load_idx(const void* ei, long long pos, int is64) {
    if (is64) return (int)((const long long*)ei)[pos];
    return ((const int*)ei)[pos];
}

// ---------------- prep (nan_to_num -> xin, float4) + count degrees -----------
__global__ void prepcount_kernel(const float* __restrict__ x,
                                 const void* __restrict__ ei) {
    __shared__ int s_is64;
    int is64 = detect_is64_block(ei, &s_is64);
    int i = blockIdx.x * blockDim.x + threadIdx.x;
    if (i < N_NODES * CH / 4) {
        float4 v = ((const float4*)x)[i];
        v.x = isnan(v.x) ? 0.f : v.x;
        v.y = isnan(v.y) ? 0.f : v.y;
        v.z = isnan(v.z) ? 0.f : v.z;
        v.w = isnan(v.w) ? 0.f : v.w;
        ((float4*)g_xin)[i] = v;
    }
    if (i < N_EDGES) {
        int d = load_idx(ei, (long long)N_EDGES + i, is64);
        atomicAdd(&g_deg[d], 1);
    }
}

// ---------------- single-pass scan with decoupled lookback -------------------
__device__ __forceinline__ int block_incl_scan(int v, int* warp_sums) {
    int tid = threadIdx.x, lane = tid & 31, w = tid >> 5;
    int nw = blockDim.x >> 5;
    int incl = v;
    #pragma unroll
    for (int d = 1; d < 32; d <<= 1) {
        int t = __shfl_up_sync(0xffffffffu, incl, d);
        if (lane >= d) incl += t;
    }
    if (lane == 31) warp_sums[w] = incl;
    __syncthreads();
    if (w == 0) {
        int ws = (lane < nw) ? warp_sums[lane] : 0;
        #pragma unroll
        for (int d = 1; d < 32; d <<= 1) {
            int t = __shfl_up_sync(0xffffffffu, ws, d);
            if (lane >= d) ws += t;
        }
        if (lane < nw) warp_sums[lane] = ws;
    }
    __syncthreads();
    return incl + (w > 0 ? warp_sums[w - 1] : 0);
}

// All NB=98 blocks are co-resident on 148 SMs (wave 1), so the lookback spin
// cannot starve. Statuses are reset by fill_kernel (next launch in stream);
// g_deg is re-zeroed here for the next kernel_launch call.
__global__ void __launch_bounds__(SCAN_B) scan_kernel() {
    __shared__ int warp_sums[32];
    __shared__ int s_excl;
    int b = blockIdx.x, tid = threadIdx.x;
    int i = b * SCAN_B + tid;
    int v = (i < N_NODES) ? g_deg[i] : 0;
    int incl = block_incl_scan(v, warp_sums);

    if (tid == SCAN_B - 1) {           // incl here == block total
        if (b == 0) {
            *((volatile int*)&g_blk_inc[0]) = incl;
            __threadfence();
            atomicExch(&g_blk_stat[0], 2);
        } else {
            *((volatile int*)&g_blk_agg[b]) = incl;
            __threadfence();
            atomicExch(&g_blk_stat[b], 1);
        }
    }
    if (tid == 0) {
        int excl = 0;
        if (b > 0) {
            int p = b - 1;
            while (true) {
                int s;
                do { s = atomicAdd(&g_blk_stat[p], 0); } while (s == 0);
                __threadfence();
                if (s == 2) { excl += *((volatile int*)&g_blk_inc[p]); break; }
                excl += *((volatile int*)&g_blk_agg[p]);
                --p;
            }
        }
        s_excl = excl;
    }
    __syncthreads();
    int excl = s_excl;
    if (tid == SCAN_B - 1 && b > 0) {
        *((volatile int*)&g_blk_inc[b]) = excl + incl;
        __threadfence();
        atomicExch(&g_blk_stat[b], 2);
    }
    if (i < N_NODES) {
        int ig = incl + excl;
        g_rowstart[i + 1] = ig;
        g_fill[i] = ig - v;            // exclusive position for fill phase
        g_deg[i] = 0;                  // self-restore for next launch
    }
    if (i == 0) g_rowstart[0] = 0;
}

// ---------------- fill CSR (counting sort of src by dst) + reset scan flags --
__global__ void fill_kernel(const void* __restrict__ ei) {
    __shared__ int s_is64;
    int is64 = detect_is64_block(ei, &s_is64);
    int e = blockIdx.x * blockDim.x + threadIdx.x;
    if (e < NB) g_blk_stat[e] = 0;     // reset lookback statuses for next launch
    if (e < N_EDGES) {
        int s = load_idx(ei, e, is64);
        int d = load_idx(ei, (long long)N_EDGES + e, is64);
        int pos = atomicAdd(&g_fill[d], 1);
        g_src_sorted[pos] = s;
    }
}

// ---------------- fused: segment-mean + split-bf16 MMA dense (+optional fc) --
#define SA_STRIDE 72     // bf16 per A row -> 36 words
#define SB_STRIDE 136    // bf16 per B^T row -> 68 words
#define SA_ELEMS (128 * SA_STRIDE)
#define SB_ELEMS (64 * SB_STRIDE)
#define DENSE_SMEM ((2 * SA_ELEMS + 2 * SB_ELEMS) * 2)   // 71680 bytes

__device__ __forceinline__ void mma16816(float* c, const uint32_t* a, const uint32_t* b) {
    asm volatile(
        "mma.sync.aligned.m16n8k16.row.col.f32.bf16.bf16.f32 "
        "{%0,%1,%2,%3}, {%4,%5,%6,%7}, {%8,%9}, {%0,%1,%2,%3};"
        : "+f"(c[0]), "+f"(c[1]), "+f"(c[2]), "+f"(c[3])
        : "r"(a[0]), "r"(a[1]), "r"(a[2]), "r"(a[3]), "r"(b[0]), "r"(b[1]));
}

__device__ __forceinline__ void split_bf16(float v, __nv_bfloat16& hi, __nv_bfloat16& lo) {
    hi = __float2bfloat16_rn(v);
    lo = __float2bfloat16_rn(v - __bfloat162float(hi));
}

__global__ void __launch_bounds__(256, 3) fused_layer_kernel(
    const float* __restrict__ gfeat,
    const float* __restrict__ Wl, const float* __restrict__ Wr,
    const float* __restrict__ bias,
    const float* __restrict__ Wfc, const float* __restrict__ bfc,
    float* __restrict__ out, int do_fc) {
    extern __shared__ __nv_bfloat16 smem[];
    __nv_bfloat16* sAhi = smem;
    __nv_bfloat16* sAlo = smem + SA_ELEMS;
    __nv_bfloat16* sBhi = smem + 2 * SA_ELEMS;
    __nv_bfloat16* sBlo = smem + 2 * SA_ELEMS + SB_ELEMS;
    uint32_t* uAhi = (uint32_t*)sAhi;
    uint32_t* uAlo = (uint32_t*)sAlo;
    uint32_t* uBhi = (uint32_t*)sBhi;
    uint32_t* uBlo = (uint32_t*)sBlo;

    int tid = threadIdx.x;
    int w = tid >> 5, lane = tid & 31;
    int base = blockIdx.x * 128;
    int cgrp = lane & 3;
    int rIn = lane >> 2;

    // ---- stage weights transposed + split: sB[n][k], Wl k 0..63, Wr k 64..127
    for (int idx = tid; idx < 64 * 64; idx += 256) {
        int k = idx >> 6, n = idx & 63;
        __nv_bfloat16 hi, lo;
        split_bf16(Wl[idx], hi, lo);
        sBhi[n * SB_STRIDE + k] = hi;
        sBlo[n * SB_STRIDE + k] = lo;
        split_bf16(Wr[idx], hi, lo);
        sBhi[n * SB_STRIDE + 64 + k] = hi;
        sBlo[n * SB_STRIDE + 64 + k] = lo;
    }

    // ---- phase 0 staging: gather + mean, unroll-4 edge loop -----------------
    {
        int row0 = w * 16;
        for (int i = 0; i < 16; ++i) {
            int node = base + row0 + i;
            float ax = 0.f, ay = 0.f, bx = 0.f, by = 0.f;
            if (node < N_NODES) {
                int beg = g_rowstart[node];
                int end = g_rowstart[node + 1];
                int e = beg;
                for (; e + 3 < end; e += 4) {
                    int s0 = g_src_sorted[e];
                    int s1 = g_src_sorted[e + 1];
                    int s2 = g_src_sorted[e + 2];
                    int s3 = g_src_sorted[e + 3];
                    float2 v0 = ((const float2*)(gfeat + (long long)s0 * CH))[lane];
                    float2 v1 = ((const float2*)(gfeat + (long long)s1 * CH))[lane];
                    float2 v2 = ((const float2*)(gfeat + (long long)s2 * CH))[lane];
                    float2 v3 = ((const float2*)(gfeat + (long long)s3 * CH))[lane];
                    ax += v0.x; ay += v0.y;
                    bx += v1.x; by += v1.y;
                    ax += v2.x; ay += v2.y;
                    bx += v3.x; by += v3.y;
                }
                for (; e < end; ++e) {
                    int s0 = g_src_sorted[e];
                    float2 v0 = ((const float2*)(gfeat + (long long)s0 * CH))[lane];
                    ax += v0.x; ay += v0.y;
                }
                ax += bx; ay += by;
                float inv = 1.0f / (float)max(end - beg, 1);
                ax *= inv; ay *= inv;
            }
            __nv_bfloat16 h0, l0, h1, l1;
            split_bf16(ax, h0, l0); split_bf16(ay, h1, l1);
            __nv_bfloat162 ph; ph.x = h0; ph.y = h1;
            __nv_bfloat162 pl; pl.x = l0; pl.y = l1;
            uAhi[(row0 + i) * (SA_STRIDE / 2) + lane] = *(uint32_t*)&ph;
            uAlo[(row0 + i) * (SA_STRIDE / 2) + lane] = *(uint32_t*)&pl;
        }
    }

    // ---- bias into acc ------------------------------------------------------
    float acc[8][4];
    #pragma unroll
    for (int nt = 0; nt < 8; ++nt) {
        int ch = nt * 8 + 2 * cgrp;
        float bv0 = bias[ch], bv1 = bias[ch + 1];
        acc[nt][0] = bv0; acc[nt][1] = bv1;
        acc[nt][2] = bv0; acc[nt][3] = bv1;
    }

    __syncthreads();

    #pragma unroll
    for (int phase = 0; phase < 2; ++phase) {
        if (phase == 1) {
            __syncthreads();   // phase-0 readers done before overwrite
            // stage root features: thread t -> row t>>1, half t&1 (8 float4)
            int row = tid >> 1, half = tid & 1;
            int node = base + row;
            bool valid = node < N_NODES;
            const float4* src = (const float4*)(gfeat + (long long)node * CH) + half * 8;
            int wbase = row * (SA_STRIDE / 2) + half * 16;
            #pragma unroll
            for (int q = 0; q < 8; ++q) {
                float4 v = valid ? src[q] : make_float4(0.f, 0.f, 0.f, 0.f);
                __nv_bfloat16 h0, l0, h1, l1, h2, l2, h3, l3;
                split_bf16(v.x, h0, l0); split_bf16(v.y, h1, l1);
                split_bf16(v.z, h2, l2); split_bf16(v.w, h3, l3);
                __nv_bfloat162 ph0; ph0.x = h0; ph0.y = h1;
                __nv_bfloat162 ph1; ph1.x = h2; ph1.y = h3;
                __nv_bfloat162 pl0; pl0.x = l0; pl0.y = l1;
                __nv_bfloat162 pl1; pl1.x = l2; pl1.y = l3;
                uAhi[wbase + q * 2]     = *(uint32_t*)&ph0;
                uAhi[wbase + q * 2 + 1] = *(uint32_t*)&ph1;
                uAlo[wbase + q * 2]     = *(uint32_t*)&pl0;
                uAlo[wbase + q * 2 + 1] = *(uint32_t*)&pl1;
            }
            __syncthreads();
        }

        // ---- mma main loop: K=64 in 4 k16 steps (conflict-free scalar LDS) --
        #pragma unroll
        for (int s = 0; s < 4; ++s) {
            uint32_t ah[4], al[4];
            int row = w * 16 + rIn;
            int wb = row * (SA_STRIDE / 2) + s * 8 + cgrp;
            const int R8 = 8 * (SA_STRIDE / 2);
            ah[0] = uAhi[wb];       ah[1] = uAhi[wb + R8];
            ah[2] = uAhi[wb + 4];   ah[3] = uAhi[wb + R8 + 4];
            al[0] = uAlo[wb];       al[1] = uAlo[wb + R8];
            al[2] = uAlo[wb + 4];   al[3] = uAlo[wb + R8 + 4];
            #pragma unroll
            for (int nt = 0; nt < 8; ++nt) {
                int n = nt * 8 + (lane >> 2);
                int bw = n * (SB_STRIDE / 2) + phase * 32 + s * 8 + cgrp;
                uint32_t bh[2] = { uBhi[bw], uBhi[bw + 4] };
                uint32_t bl[2] = { uBlo[bw], uBlo[bw + 4] };
                mma16816(acc[nt], ah, bh);
                mma16816(acc[nt], ah, bl);
                mma16816(acc[nt], al, bh);
            }
        }
    }

    // ---- epilogue -----------------------------------------------------------
    int r0 = base + w * 16 + rIn;
    int r1 = r0 + 8;
    if (do_fc) {
        float p0 = 0.f, p1 = 0.f;
        #pragma unroll
        for (int nt = 0; nt < 8; ++nt) {
            int ch = nt * 8 + 2 * cgrp;
            float w0 = Wfc[ch], w1 = Wfc[ch + 1];
            p0 += fmaxf(acc[nt][0], 0.f) * w0 + fmaxf(acc[nt][1], 0.f) * w1;
            p1 += fmaxf(acc[nt][2], 0.f) * w0 + fmaxf(acc[nt][3], 0.f) * w1;
        }
        p0 += __shfl_xor_sync(0xffffffffu, p0, 1);
        p0 += __shfl_xor_sync(0xffffffffu, p0, 2);
        p1 += __shfl_xor_sync(0xffffffffu, p1, 1);
        p1 += __shfl_xor_sync(0xffffffffu, p1, 2);
        if (cgrp == 0) {
            float bv = bfc[0];
            if (r0 < N_NODES) out[r0] = p0 + bv;
            if (r1 < N_NODES) out[r1] = p1 + bv;
        }
    } else {
        #pragma unroll
        for (int nt = 0; nt < 8; ++nt) {
            int ch = nt * 8 + 2 * cgrp;
            if (r0 < N_NODES) {
                float2 v = make_float2(fmaxf(acc[nt][0], 0.f),
                                       fmaxf(acc[nt][1], 0.f));
                *(float2*)(out + (long long)r0 * CH + ch) = v;
            }
            if (r1 < N_NODES) {
                float2 v = make_float2(fmaxf(acc[nt][2], 0.f),
                                       fmaxf(acc[nt][3], 0.f));
                *(float2*)(out + (long long)r1 * CH + ch) = v;
            }
        }
    }
}

// ---------------- launch -----------------------------------------------------
extern "C" void kernel_launch(void* const* d_in, const int* in_sizes, int n_in,
                              void* d_out, int out_size) {
    const float* x   = (const float*)d_in[0];
    const void*  ei  = d_in[1];
    const float* W1l = (const float*)d_in[2];
    const float* b1  = (const float*)d_in[3];
    const float* W1r = (const float*)d_in[4];
    const float* W2l = (const float*)d_in[5];
    const float* b2  = (const float*)d_in[6];
    const float* W2r = (const float*)d_in[7];
    const float* Wfc = (const float*)d_in[8];
    const float* bfc = (const float*)d_in[9];
    float* out = (float*)d_out;

    float *xin, *h1;
    cudaGetSymbolAddress((void**)&xin, g_xin);
    cudaGetSymbolAddress((void**)&h1,  g_h1);

    cudaFuncSetAttribute(fused_layer_kernel,
                         cudaFuncAttributeMaxDynamicSharedMemorySize, DENSE_SMEM);

    const int T = 256;
    int gridPC   = (N_NODES * CH / 4 + T - 1) / T;
    int gridEdge = (N_EDGES + T - 1) / T;
    int gridFuse = (N_NODES + 127) / 128;

    prepcount_kernel<<<gridPC, T>>>(x, ei);
    scan_kernel<<<NB, SCAN_B>>>();
    fill_kernel<<<gridEdge, T>>>(ei);

    fused_layer_kernel<<<gridFuse, 256, DENSE_SMEM>>>(xin, W1l, W1r, b1,
                                                      Wfc, bfc, h1, 0);
    fused_layer_kernel<<<gridFuse, 256, DENSE_SMEM>>>(h1, W2l, W2r, b2,
                                                      Wfc, bfc, out, 1);
}

// round 9
// speedup vs baseline: 1.1404x; 1.1404x over previous
#include <cuda_runtime.h>
#include <cuda_bf16.h>
#include <math.h>
#include <stdint.h>

#define N_NODES 100000
#define N_EDGES 1200000
#define CH 64
#define SCAN_B 1024
#define NB ((N_NODES + SCAN_B - 1) / SCAN_B)   // 98 blocks

// ---------------- scratch (static device memory; no allocs allowed) ----------
__device__ float          g_xin[N_NODES * CH];
__device__ float          g_h1 [N_NODES * CH];
__device__ __nv_bfloat16  g_mhi[N_NODES * CH];   // mean, hi bf16 plane
__device__ __nv_bfloat16  g_mlo[N_NODES * CH];   // mean, lo bf16 plane
__device__ int   g_deg [N_NODES];        // zeroed at load; scan re-zeroes after use
__device__ int   g_rowstart[N_NODES + 1];
__device__ int   g_fill[N_NODES];
__device__ int   g_src_sorted[N_EDGES];
__device__ int   g_blk_stat[NB];         // 0 pending, 1 agg, 2 incl; fill resets
__device__ int   g_blk_agg[NB];
__device__ int   g_blk_inc[NB];

// ---------------- per-block edge dtype detection (warp ballot) ---------------
__device__ __forceinline__ int detect_is64_block(const void* ei, int* s_flag) {
    int tid = threadIdx.x;
    if (tid < 32) {
        const int* w = (const int*)ei;
        int ok = (w[2 * tid + 1] == 0) && (w[2 * (tid + 32) + 1] == 0);
        unsigned m = __ballot_sync(0xffffffffu, ok);
        if (tid == 0) *s_flag = (m == 0xffffffffu);
    }
    __syncthreads();
    return *s_flag;
}

__device__ __forceinline__ int load_idx(const void* ei, long long pos, int is64) {
    if (is64) return (int)((const long long*)ei)[pos];
    return ((const int*)ei)[pos];
}

// ---------------- prep (nan_to_num -> xin, float4) + count degrees -----------
__global__ void prepcount_kernel(const float* __restrict__ x,
                                 const void* __restrict__ ei) {
    __shared__ int s_is64;
    int is64 = detect_is64_block(ei, &s_is64);
    int i = blockIdx.x * blockDim.x + threadIdx.x;
    if (i < N_NODES * CH / 4) {
        float4 v = ((const float4*)x)[i];
        v.x = isnan(v.x) ? 0.f : v.x;
        v.y = isnan(v.y) ? 0.f : v.y;
        v.z = isnan(v.z) ? 0.f : v.z;
        v.w = isnan(v.w) ? 0.f : v.w;
        ((float4*)g_xin)[i] = v;
    }
    if (i < N_EDGES) {
        int d = load_idx(ei, (long long)N_EDGES + i, is64);
        atomicAdd(&g_deg[d], 1);
    }
}

// ---------------- single-pass scan with decoupled lookback -------------------
__device__ __forceinline__ int block_incl_scan(int v, int* warp_sums) {
    int tid = threadIdx.x, lane = tid & 31, w = tid >> 5;
    int nw = blockDim.x >> 5;
    int incl = v;
    #pragma unroll
    for (int d = 1; d < 32; d <<= 1) {
        int t = __shfl_up_sync(0xffffffffu, incl, d);
        if (lane >= d) incl += t;
    }
    if (lane == 31) warp_sums[w] = incl;
    __syncthreads();
    if (w == 0) {
        int ws = (lane < nw) ? warp_sums[lane] : 0;
        #pragma unroll
        for (int d = 1; d < 32; d <<= 1) {
            int t = __shfl_up_sync(0xffffffffu, ws, d);
            if (lane >= d) ws += t;
        }
        if (lane < nw) warp_sums[lane] = ws;
    }
    __syncthreads();
    return incl + (w > 0 ? warp_sums[w - 1] : 0);
}

__global__ void __launch_bounds__(SCAN_B) scan_kernel() {
    __shared__ int warp_sums[32];
    __shared__ int s_excl;
    int b = blockIdx.x, tid = threadIdx.x;
    int i = b * SCAN_B + tid;
    int v = (i < N_NODES) ? g_deg[i] : 0;
    int incl = block_incl_scan(v, warp_sums);

    if (tid == SCAN_B - 1) {           // incl == block total here
        if (b == 0) {
            *((volatile int*)&g_blk_inc[0]) = incl;
            __threadfence();
            atomicExch(&g_blk_stat[0], 2);
        } else {
            *((volatile int*)&g_blk_agg[b]) = incl;
            __threadfence();
            atomicExch(&g_blk_stat[b], 1);
        }
    }
    if (tid == 0) {
        int excl = 0;
        if (b > 0) {
            int p = b - 1;
            while (true) {
                int s;
                do { s = atomicAdd(&g_blk_stat[p], 0); } while (s == 0);
                __threadfence();
                if (s == 2) { excl += *((volatile int*)&g_blk_inc[p]); break; }
                excl += *((volatile int*)&g_blk_agg[p]);
                --p;
            }
        }
        s_excl = excl;
    }
    __syncthreads();
    int excl = s_excl;
    if (tid == SCAN_B - 1 && b > 0) {
        *((volatile int*)&g_blk_inc[b]) = excl + incl;
        __threadfence();
        atomicExch(&g_blk_stat[b], 2);
    }
    if (i < N_NODES) {
        int ig = incl + excl;
        g_rowstart[i + 1] = ig;
        g_fill[i] = ig - v;
        g_deg[i] = 0;                  // self-restore for next launch
    }
    if (i == 0) g_rowstart[0] = 0;
}

// ---------------- fill CSR + reset scan flags --------------------------------
__global__ void fill_kernel(const void* __restrict__ ei) {
    __shared__ int s_is64;
    int is64 = detect_is64_block(ei, &s_is64);
    int e = blockIdx.x * blockDim.x + threadIdx.x;
    if (e < NB) g_blk_stat[e] = 0;
    if (e < N_EDGES) {
        int s = load_idx(ei, e, is64);
        int d = load_idx(ei, (long long)N_EDGES + e, is64);
        int pos = atomicAdd(&g_fill[d], 1);
        g_src_sorted[pos] = s;
    }
}

// ---------------- split helper -----------------------------------------------
__device__ __forceinline__ void split_bf16(float v, __nv_bfloat16& hi, __nv_bfloat16& lo) {
    hi = __float2bfloat16_rn(v);
    lo = __float2bfloat16_rn(v - __bfloat162float(hi));
}

// ---------------- segment mean: one warp/node, writes split bf16 planes ------
__global__ void __launch_bounds__(256) segmean_kernel(const float* __restrict__ feat) {
    int node = (blockIdx.x * blockDim.x + threadIdx.x) >> 5;
    if (node >= N_NODES) return;
    int lane = threadIdx.x & 31;
    int beg = g_rowstart[node];
    int end = g_rowstart[node + 1];
    float ax = 0.f, ay = 0.f, bx = 0.f, by = 0.f;
    int e = beg;
    for (; e + 3 < end; e += 4) {
        int s0 = g_src_sorted[e];
        int s1 = g_src_sorted[e + 1];
        int s2 = g_src_sorted[e + 2];
        int s3 = g_src_sorted[e + 3];
        float2 v0 = ((const float2*)(feat + (long long)s0 * CH))[lane];
        float2 v1 = ((const float2*)(feat + (long long)s1 * CH))[lane];
        float2 v2 = ((const float2*)(feat + (long long)s2 * CH))[lane];
        float2 v3 = ((const float2*)(feat + (long long)s3 * CH))[lane];
        ax += v0.x; ay += v0.y;
        bx += v1.x; by += v1.y;
        ax += v2.x; ay += v2.y;
        bx += v3.x; by += v3.y;
    }
    for (; e < end; ++e) {
        int s0 = g_src_sorted[e];
        float2 v0 = ((const float2*)(feat + (long long)s0 * CH))[lane];
        ax += v0.x; ay += v0.y;
    }
    ax += bx; ay += by;
    float inv = 1.0f / (float)max(end - beg, 1);
    ax *= inv; ay *= inv;
    __nv_bfloat16 h0, l0, h1, l1;
    split_bf16(ax, h0, l0); split_bf16(ay, h1, l1);
    __nv_bfloat162 ph; ph.x = h0; ph.y = h1;
    __nv_bfloat162 pl; pl.x = l0; pl.y = l1;
    ((uint32_t*)g_mhi)[node * 32 + lane] = *(uint32_t*)&ph;
    ((uint32_t*)g_mlo)[node * 32 + lane] = *(uint32_t*)&pl;
}

// ---------------- dense: split-bf16 MMA, A-mean from pre-split planes --------
#define SA_STRIDE 72     // bf16 per A row -> 36 words
#define SB_STRIDE 136    // bf16 per B^T row -> 68 words
#define SA_ELEMS (128 * SA_STRIDE)
#define SB_ELEMS (64 * SB_STRIDE)
#define DENSE_SMEM ((2 * SA_ELEMS + 2 * SB_ELEMS) * 2)   // 71680 bytes

__device__ __forceinline__ void mma16816(float* c, const uint32_t* a, const uint32_t* b) {
    asm volatile(
        "mma.sync.aligned.m16n8k16.row.col.f32.bf16.bf16.f32 "
        "{%0,%1,%2,%3}, {%4,%5,%6,%7}, {%8,%9}, {%0,%1,%2,%3};"
        : "+f"(c[0]), "+f"(c[1]), "+f"(c[2]), "+f"(c[3])
        : "r"(a[0]), "r"(a[1]), "r"(a[2]), "r"(a[3]), "r"(b[0]), "r"(b[1]));
}

__global__ void __launch_bounds__(256) dense_mma_kernel(
    const float* __restrict__ root,
    const float* __restrict__ Wl, const float* __restrict__ Wr,
    const float* __restrict__ bias,
    const float* __restrict__ Wfc, const float* __restrict__ bfc,
    float* __restrict__ out, int do_fc) {
    extern __shared__ __nv_bfloat16 smem[];
    __nv_bfloat16* sAhi = smem;
    __nv_bfloat16* sAlo = smem + SA_ELEMS;
    __nv_bfloat16* sBhi = smem + 2 * SA_ELEMS;
    __nv_bfloat16* sBlo = smem + 2 * SA_ELEMS + SB_ELEMS;
    uint32_t* uAhi = (uint32_t*)sAhi;
    uint32_t* uAlo = (uint32_t*)sAlo;
    uint32_t* uBhi = (uint32_t*)sBhi;
    uint32_t* uBlo = (uint32_t*)sBlo;

    int tid = threadIdx.x;
    int w = tid >> 5, lane = tid & 31;
    int base = blockIdx.x * 128;
    int cgrp = lane & 3;
    int rIn = lane >> 2;

    // ---- stage weights transposed + split: sB[n][k], Wl k 0..63, Wr k 64..127
    for (int idx = tid; idx < 64 * 64; idx += 256) {
        int k = idx >> 6, n = idx & 63;
        __nv_bfloat16 hi, lo;
        split_bf16(Wl[idx], hi, lo);
        sBhi[n * SB_STRIDE + k] = hi;
        sBlo[n * SB_STRIDE + k] = lo;
        split_bf16(Wr[idx], hi, lo);
        sBhi[n * SB_STRIDE + 64 + k] = hi;
        sBlo[n * SB_STRIDE + 64 + k] = lo;
    }

    // ---- stage A-mean: straight uint4 copies from pre-split planes ----------
    // thread t: row = t>>1, half = t&1; 4 uint4 per plane (64 B)
    {
        int row = tid >> 1, half = tid & 1;
        int node = base + row;
        bool valid = node < N_NODES;
        const uint4* shi = (const uint4*)((const uint32_t*)g_mhi + (long long)node * 32) + half * 4;
        const uint4* slo = (const uint4*)((const uint32_t*)g_mlo + (long long)node * 32) + half * 4;
        int wb = row * (SA_STRIDE / 2) + half * 16;
        #pragma unroll
        for (int q = 0; q < 4; ++q) {
            uint4 vh = valid ? shi[q] : make_uint4(0, 0, 0, 0);
            uint4 vl = valid ? slo[q] : make_uint4(0, 0, 0, 0);
            *(uint4*)&uAhi[wb + q * 4] = vh;
            *(uint4*)&uAlo[wb + q * 4] = vl;
        }
    }

    // ---- bias into acc ------------------------------------------------------
    float acc[8][4];
    #pragma unroll
    for (int nt = 0; nt < 8; ++nt) {
        int ch = nt * 8 + 2 * cgrp;
        float bv0 = bias[ch], bv1 = bias[ch + 1];
        acc[nt][0] = bv0; acc[nt][1] = bv1;
        acc[nt][2] = bv0; acc[nt][3] = bv1;
    }

    __syncthreads();

    #pragma unroll
    for (int phase = 0; phase < 2; ++phase) {
        if (phase == 1) {
            __syncthreads();   // phase-0 readers done before overwrite
            // stage root features fp32 -> split: thread t -> row t>>1, half t&1
            int row = tid >> 1, half = tid & 1;
            int node = base + row;
            bool valid = node < N_NODES;
            const float4* src = (const float4*)(root + (long long)node * CH) + half * 8;
            int wbase = row * (SA_STRIDE / 2) + half * 16;
            #pragma unroll
            for (int q = 0; q < 8; ++q) {
                float4 v = valid ? src[q] : make_float4(0.f, 0.f, 0.f, 0.f);
                __nv_bfloat16 h0, l0, h1, l1, h2, l2, h3, l3;
                split_bf16(v.x, h0, l0); split_bf16(v.y, h1, l1);
                split_bf16(v.z, h2, l2); split_bf16(v.w, h3, l3);
                __nv_bfloat162 ph0; ph0.x = h0; ph0.y = h1;
                __nv_bfloat162 ph1; ph1.x = h2; ph1.y = h3;
                __nv_bfloat162 pl0; pl0.x = l0; pl0.y = l1;
                __nv_bfloat162 pl1; pl1.x = l2; pl1.y = l3;
                uAhi[wbase + q * 2]     = *(uint32_t*)&ph0;
                uAhi[wbase + q * 2 + 1] = *(uint32_t*)&ph1;
                uAlo[wbase + q * 2]     = *(uint32_t*)&pl0;
                uAlo[wbase + q * 2 + 1] = *(uint32_t*)&pl1;
            }
            __syncthreads();
        }

        // ---- mma main loop: K=64 in 4 k16 steps (conflict-free scalar LDS) --
        #pragma unroll
        for (int s = 0; s < 4; ++s) {
            uint32_t ah[4], al[4];
            int row = w * 16 + rIn;
            int wb = row * (SA_STRIDE / 2) + s * 8 + cgrp;
            const int R8 = 8 * (SA_STRIDE / 2);
            ah[0] = uAhi[wb];       ah[1] = uAhi[wb + R8];
            ah[2] = uAhi[wb + 4];   ah[3] = uAhi[wb + R8 + 4];
            al[0] = uAlo[wb];       al[1] = uAlo[wb + R8];
            al[2] = uAlo[wb + 4];   al[3] = uAlo[wb + R8 + 4];
            #pragma unroll
            for (int nt = 0; nt < 8; ++nt) {
                int n = nt * 8 + (lane >> 2);
                int bw = n * (SB_STRIDE / 2) + phase * 32 + s * 8 + cgrp;
                uint32_t bh[2] = { uBhi[bw], uBhi[bw + 4] };
                uint32_t bl[2] = { uBlo[bw], uBlo[bw + 4] };
                mma16816(acc[nt], ah, bh);
                mma16816(acc[nt], ah, bl);
                mma16816(acc[nt], al, bh);
            }
        }
    }

    // ---- epilogue -----------------------------------------------------------
    int r0 = base + w * 16 + rIn;
    int r1 = r0 + 8;
    if (do_fc) {
        float p0 = 0.f, p1 = 0.f;
        #pragma unroll
        for (int nt = 0; nt < 8; ++nt) {
            int ch = nt * 8 + 2 * cgrp;
            float w0 = Wfc[ch], w1 = Wfc[ch + 1];
            p0 += fmaxf(acc[nt][0], 0.f) * w0 + fmaxf(acc[nt][1], 0.f) * w1;
            p1 += fmaxf(acc[nt][2], 0.f) * w0 + fmaxf(acc[nt][3], 0.f) * w1;
        }
        p0 += __shfl_xor_sync(0xffffffffu, p0, 1);
        p0 += __shfl_xor_sync(0xffffffffu, p0, 2);
        p1 += __shfl_xor_sync(0xffffffffu, p1, 1);
        p1 += __shfl_xor_sync(0xffffffffu, p1, 2);
        if (cgrp == 0) {
            float bv = bfc[0];
            if (r0 < N_NODES) out[r0] = p0 + bv;
            if (r1 < N_NODES) out[r1] = p1 + bv;
        }
    } else {
        #pragma unroll
        for (int nt = 0; nt < 8; ++nt) {
            int ch = nt * 8 + 2 * cgrp;
            if (r0 < N_NODES) {
                float2 v = make_float2(fmaxf(acc[nt][0], 0.f),
                                       fmaxf(acc[nt][1], 0.f));
                *(float2*)(out + (long long)r0 * CH + ch) = v;
            }
            if (r1 < N_NODES) {
                float2 v = make_float2(fmaxf(acc[nt][2], 0.f),
                                       fmaxf(acc[nt][3], 0.f));
                *(float2*)(out + (long long)r1 * CH + ch) = v;
            }
        }
    }
}

// ---------------- launch -----------------------------------------------------
extern "C" void kernel_launch(void* const* d_in, const int* in_sizes, int n_in,
                              void* d_out, int out_size) {
    const float* x   = (const float*)d_in[0];
    const void*  ei  = d_in[1];
    const float* W1l = (const float*)d_in[2];
    const float* b1  = (const float*)d_in[3];
    const float* W1r = (const float*)d_in[4];
    const float* W2l = (const float*)d_in[5];
    const float* b2  = (const float*)d_in[6];
    const float* W2r = (const float*)d_in[7];
    const float* Wfc = (const float*)d_in[8];
    const float* bfc = (const float*)d_in[9];
    float* out = (float*)d_out;

    float *xin, *h1;
    cudaGetSymbolAddress((void**)&xin, g_xin);
    cudaGetSymbolAddress((void**)&h1,  g_h1);

    cudaFuncSetAttribute(dense_mma_kernel,
                         cudaFuncAttributeMaxDynamicSharedMemorySize, DENSE_SMEM);

    const int T = 256;
    int gridPC    = (N_NODES * CH / 4 + T - 1) / T;
    int gridEdge  = (N_EDGES + T - 1) / T;
    int gridWarp  = (N_NODES * 32 + T - 1) / T;   // one warp per node
    int gridDense = (N_NODES + 127) / 128;

    prepcount_kernel<<<gridPC, T>>>(x, ei);
    scan_kernel<<<NB, SCAN_B>>>();
    fill_kernel<<<gridEdge, T>>>(ei);

    // layer 1
    segmean_kernel<<<gridWarp, T>>>(xin);
    dense_mma_kernel<<<gridDense, T, DENSE_SMEM>>>(xin, W1l, W1r, b1,
                                                   Wfc, bfc, h1, 0);
    // layer 2 (+ fused fc head)
    segmean_kernel<<<gridWarp, T>>>(h1);
    dense_mma_kernel<<<gridDense, T, DENSE_SMEM>>>(h1, W2l, W2r, b2,
                                                   Wfc, bfc, out, 1);
}

// round 10
// speedup vs baseline: 1.1631x; 1.0199x over previous
#include <cuda_runtime.h>
#include <cuda_bf16.h>
#include <math.h>
#include <stdint.h>

#define N_NODES 100000
#define N_EDGES 1200000
#define CH 64
#define SCAN_B 1024
#define NB ((N_NODES + SCAN_B - 1) / SCAN_B)   // 98 blocks

// ---------------- scratch (static device memory; no allocs allowed) ----------
__device__ float          g_h1 [N_NODES * CH];
__device__ __nv_bfloat16  g_mhi[N_NODES * CH];   // mean, hi bf16 plane
__device__ __nv_bfloat16  g_mlo[N_NODES * CH];   // mean, lo bf16 plane
__device__ int   g_deg [N_NODES];        // zeroed at load; scan re-zeroes after use
__device__ int   g_rowstart[N_NODES + 1];
__device__ int   g_fill[N_NODES];
__device__ int   g_src_sorted[N_EDGES];
__device__ int   g_blk_stat[NB];         // 0 pending, 1 agg, 2 incl; fill resets
__device__ int   g_blk_agg[NB];
__device__ int   g_blk_inc[NB];

// ---------------- per-block edge dtype detection (warp ballot) ---------------
__device__ __forceinline__ int detect_is64_block(const void* ei, int* s_flag) {
    int tid = threadIdx.x;
    if (tid < 32) {
        const int* w = (const int*)ei;
        int ok = (w[2 * tid + 1] == 0) && (w[2 * (tid + 32) + 1] == 0);
        unsigned m = __ballot_sync(0xffffffffu, ok);
        if (tid == 0) *s_flag = (m == 0xffffffffu);
    }
    __syncthreads();
    return *s_flag;
}

__device__ __forceinline__ int load_idx(const void* ei, long long pos, int is64) {
    if (is64) return (int)((const long long*)ei)[pos];
    return ((const int*)ei)[pos];
}

// ---------------- count degrees (dst half of edge_index only) ----------------
__global__ void count_kernel(const void* __restrict__ ei) {
    __shared__ int s_is64;
    int is64 = detect_is64_block(ei, &s_is64);
    int e = blockIdx.x * blockDim.x + threadIdx.x;
    if (e < N_EDGES) {
        int d = load_idx(ei, (long long)N_EDGES + e, is64);
        atomicAdd(&g_deg[d], 1);
    }
}

// ---------------- single-pass scan with decoupled lookback -------------------
__device__ __forceinline__ int block_incl_scan(int v, int* warp_sums) {
    int tid = threadIdx.x, lane = tid & 31, w = tid >> 5;
    int nw = blockDim.x >> 5;
    int incl = v;
    #pragma unroll
    for (int d = 1; d < 32; d <<= 1) {
        int t = __shfl_up_sync(0xffffffffu, incl, d);
        if (lane >= d) incl += t;
    }
    if (lane == 31) warp_sums[w] = incl;
    __syncthreads();
    if (w == 0) {
        int ws = (lane < nw) ? warp_sums[lane] : 0;
        #pragma unroll
        for (int d = 1; d < 32; d <<= 1) {
            int t = __shfl_up_sync(0xffffffffu, ws, d);
            if (lane >= d) ws += t;
        }
        if (lane < nw) warp_sums[lane] = ws;
    }
    __syncthreads();
    return incl + (w > 0 ? warp_sums[w - 1] : 0);
}

__global__ void __launch_bounds__(SCAN_B) scan_kernel() {
    __shared__ int warp_sums[32];
    __shared__ int s_excl;
    int b = blockIdx.x, tid = threadIdx.x;
    int i = b * SCAN_B + tid;
    int v = (i < N_NODES) ? g_deg[i] : 0;
    int incl = block_incl_scan(v, warp_sums);

    if (tid == SCAN_B - 1) {           // incl == block total here
        if (b == 0) {
            *((volatile int*)&g_blk_inc[0]) = incl;
            __threadfence();
            atomicExch(&g_blk_stat[0], 2);
        } else {
            *((volatile int*)&g_blk_agg[b]) = incl;
            __threadfence();
            atomicExch(&g_blk_stat[b], 1);
        }
    }
    if (tid == 0) {
        int excl = 0;
        if (b > 0) {
            int p = b - 1;
            while (true) {
                int s;
                do { s = atomicAdd(&g_blk_stat[p], 0); } while (s == 0);
                __threadfence();
                if (s == 2) { excl += *((volatile int*)&g_blk_inc[p]); break; }
                excl += *((volatile int*)&g_blk_agg[p]);
                --p;
            }
        }
        s_excl = excl;
    }
    __syncthreads();
    int excl = s_excl;
    if (tid == SCAN_B - 1 && b > 0) {
        *((volatile int*)&g_blk_inc[b]) = excl + incl;
        __threadfence();
        atomicExch(&g_blk_stat[b], 2);
    }
    if (i < N_NODES) {
        int ig = incl + excl;
        g_rowstart[i + 1] = ig;
        g_fill[i] = ig - v;
        g_deg[i] = 0;                  // self-restore for next launch
    }
    if (i == 0) g_rowstart[0] = 0;
}

// ---------------- fill CSR + reset scan flags --------------------------------
__global__ void fill_kernel(const void* __restrict__ ei) {
    __shared__ int s_is64;
    int is64 = detect_is64_block(ei, &s_is64);
    int e = blockIdx.x * blockDim.x + threadIdx.x;
    if (e < NB) g_blk_stat[e] = 0;
    if (e < N_EDGES) {
        int s = load_idx(ei, e, is64);
        int d = load_idx(ei, (long long)N_EDGES + e, is64);
        int pos = atomicAdd(&g_fill[d], 1);
        g_src_sorted[pos] = s;
    }
}

// ---------------- split helper -----------------------------------------------
__device__ __forceinline__ void split_bf16(float v, __nv_bfloat16& hi, __nv_bfloat16& lo) {
    hi = __float2bfloat16_rn(v);
    lo = __float2bfloat16_rn(v - __bfloat162float(hi));
}

// ---------------- segment mean: one warp/node, writes split bf16 planes ------
// unroll-8 leading loop for MLP, then unroll-4, then scalar tail.
__global__ void __launch_bounds__(256) segmean_kernel(const float* __restrict__ feat) {
    int node = (blockIdx.x * blockDim.x + threadIdx.x) >> 5;
    if (node >= N_NODES) return;
    int lane = threadIdx.x & 31;
    int beg = g_rowstart[node];
    int end = g_rowstart[node + 1];
    float ax = 0.f, ay = 0.f, bx = 0.f, by = 0.f;
    int e = beg;
    for (; e + 7 < end; e += 8) {
        int s0 = g_src_sorted[e];
        int s1 = g_src_sorted[e + 1];
        int s2 = g_src_sorted[e + 2];
        int s3 = g_src_sorted[e + 3];
        int s4 = g_src_sorted[e + 4];
        int s5 = g_src_sorted[e + 5];
        int s6 = g_src_sorted[e + 6];
        int s7 = g_src_sorted[e + 7];
        float2 v0 = ((const float2*)(feat + (long long)s0 * CH))[lane];
        float2 v1 = ((const float2*)(feat + (long long)s1 * CH))[lane];
        float2 v2 = ((const float2*)(feat + (long long)s2 * CH))[lane];
        float2 v3 = ((const float2*)(feat + (long long)s3 * CH))[lane];
        float2 v4 = ((const float2*)(feat + (long long)s4 * CH))[lane];
        float2 v5 = ((const float2*)(feat + (long long)s5 * CH))[lane];
        float2 v6 = ((const float2*)(feat + (long long)s6 * CH))[lane];
        float2 v7 = ((const float2*)(feat + (long long)s7 * CH))[lane];
        ax += v0.x; ay += v0.y;  bx += v1.x; by += v1.y;
        ax += v2.x; ay += v2.y;  bx += v3.x; by += v3.y;
        ax += v4.x; ay += v4.y;  bx += v5.x; by += v5.y;
        ax += v6.x; ay += v6.y;  bx += v7.x; by += v7.y;
    }
    for (; e + 3 < end; e += 4) {
        int s0 = g_src_sorted[e];
        int s1 = g_src_sorted[e + 1];
        int s2 = g_src_sorted[e + 2];
        int s3 = g_src_sorted[e + 3];
        float2 v0 = ((const float2*)(feat + (long long)s0 * CH))[lane];
        float2 v1 = ((const float2*)(feat + (long long)s1 * CH))[lane];
        float2 v2 = ((const float2*)(feat + (long long)s2 * CH))[lane];
        float2 v3 = ((const float2*)(feat + (long long)s3 * CH))[lane];
        ax += v0.x; ay += v0.y;  bx += v1.x; by += v1.y;
        ax += v2.x; ay += v2.y;  bx += v3.x; by += v3.y;
    }
    for (; e < end; ++e) {
        int s0 = g_src_sorted[e];
        float2 v0 = ((const float2*)(feat + (long long)s0 * CH))[lane];
        ax += v0.x; ay += v0.y;
    }
    ax += bx; ay += by;
    float inv = 1.0f / (float)max(end - beg, 1);
    ax *= inv; ay *= inv;
    __nv_bfloat16 h0, l0, h1, l1;
    split_bf16(ax, h0, l0); split_bf16(ay, h1, l1);
    __nv_bfloat162 ph; ph.x = h0; ph.y = h1;
    __nv_bfloat162 pl; pl.x = l0; pl.y = l1;
    ((uint32_t*)g_mhi)[node * 32 + lane] = *(uint32_t*)&ph;
    ((uint32_t*)g_mlo)[node * 32 + lane] = *(uint32_t*)&pl;
}

// ---------------- dense: split-bf16 MMA, A-mean from pre-split planes --------
#define SA_STRIDE 72     // bf16 per A row -> 36 words
#define SB_STRIDE 136    // bf16 per B^T row -> 68 words
#define SA_ELEMS (128 * SA_STRIDE)
#define SB_ELEMS (64 * SB_STRIDE)
#define DENSE_SMEM ((2 * SA_ELEMS + 2 * SB_ELEMS) * 2)   // 71680 bytes

__device__ __forceinline__ void mma16816(float* c, const uint32_t* a, const uint32_t* b) {
    asm volatile(
        "mma.sync.aligned.m16n8k16.row.col.f32.bf16.bf16.f32 "
        "{%0,%1,%2,%3}, {%4,%5,%6,%7}, {%8,%9}, {%0,%1,%2,%3};"
        : "+f"(c[0]), "+f"(c[1]), "+f"(c[2]), "+f"(c[3])
        : "r"(a[0]), "r"(a[1]), "r"(a[2]), "r"(a[3]), "r"(b[0]), "r"(b[1]));
}

__global__ void __launch_bounds__(256) dense_mma_kernel(
    const float* __restrict__ root,
    const float* __restrict__ Wl, const float* __restrict__ Wr,
    const float* __restrict__ bias,
    const float* __restrict__ Wfc, const float* __restrict__ bfc,
    float* __restrict__ out, int do_fc) {
    extern __shared__ __nv_bfloat16 smem[];
    __nv_bfloat16* sAhi = smem;
    __nv_bfloat16* sAlo = smem + SA_ELEMS;
    __nv_bfloat16* sBhi = smem + 2 * SA_ELEMS;
    __nv_bfloat16* sBlo = smem + 2 * SA_ELEMS + SB_ELEMS;
    uint32_t* uAhi = (uint32_t*)sAhi;
    uint32_t* uAlo = (uint32_t*)sAlo;
    uint32_t* uBhi = (uint32_t*)sBhi;
    uint32_t* uBlo = (uint32_t*)sBlo;

    int tid = threadIdx.x;
    int w = tid >> 5, lane = tid & 31;
    int base = blockIdx.x * 128;
    int cgrp = lane & 3;
    int rIn = lane >> 2;

    // ---- stage weights transposed + split: sB[n][k], Wl k 0..63, Wr k 64..127
    for (int idx = tid; idx < 64 * 64; idx += 256) {
        int k = idx >> 6, n = idx & 63;
        __nv_bfloat16 hi, lo;
        split_bf16(Wl[idx], hi, lo);
        sBhi[n * SB_STRIDE + k] = hi;
        sBlo[n * SB_STRIDE + k] = lo;
        split_bf16(Wr[idx], hi, lo);
        sBhi[n * SB_STRIDE + 64 + k] = hi;
        sBlo[n * SB_STRIDE + 64 + k] = lo;
    }

    // ---- stage A-mean: straight uint4 copies from pre-split planes ----------
    {
        int row = tid >> 1, half = tid & 1;
        int node = base + row;
        bool valid = node < N_NODES;
        const uint4* shi = (const uint4*)((const uint32_t*)g_mhi + (long long)node * 32) + half * 4;
        const uint4* slo = (const uint4*)((const uint32_t*)g_mlo + (long long)node * 32) + half * 4;
        int wb = row * (SA_STRIDE / 2) + half * 16;
        #pragma unroll
        for (int q = 0; q < 4; ++q) {
            uint4 vh = valid ? shi[q] : make_uint4(0, 0, 0, 0);
            uint4 vl = valid ? slo[q] : make_uint4(0, 0, 0, 0);
            *(uint4*)&uAhi[wb + q * 4] = vh;
            *(uint4*)&uAlo[wb + q * 4] = vl;
        }
    }

    // ---- bias into acc ------------------------------------------------------
    float acc[8][4];
    #pragma unroll
    for (int nt = 0; nt < 8; ++nt) {
        int ch = nt * 8 + 2 * cgrp;
        float bv0 = bias[ch], bv1 = bias[ch + 1];
        acc[nt][0] = bv0; acc[nt][1] = bv1;
        acc[nt][2] = bv0; acc[nt][3] = bv1;
    }

    __syncthreads();

    #pragma unroll
    for (int phase = 0; phase < 2; ++phase) {
        if (phase == 1) {
            __syncthreads();   // phase-0 readers done before overwrite
            // stage root features fp32 -> split: thread t -> row t>>1, half t&1
            int row = tid >> 1, half = tid & 1;
            int node = base + row;
            bool valid = node < N_NODES;
            const float4* src = (const float4*)(root + (long long)node * CH) + half * 8;
            int wbase = row * (SA_STRIDE / 2) + half * 16;
            #pragma unroll
            for (int q = 0; q < 8; ++q) {
                float4 v = valid ? src[q] : make_float4(0.f, 0.f, 0.f, 0.f);
                __nv_bfloat16 h0, l0, h1, l1, h2, l2, h3, l3;
                split_bf16(v.x, h0, l0); split_bf16(v.y, h1, l1);
                split_bf16(v.z, h2, l2); split_bf16(v.w, h3, l3);
                __nv_bfloat162 ph0; ph0.x = h0; ph0.y = h1;
                __nv_bfloat162 ph1; ph1.x = h2; ph1.y = h3;
                __nv_bfloat162 pl0; pl0.x = l0; pl0.y = l1;
                __nv_bfloat162 pl1; pl1.x = l2; pl1.y = l3;
                uAhi[wbase + q * 2]     = *(uint32_t*)&ph0;
                uAhi[wbase + q * 2 + 1] = *(uint32_t*)&ph1;
                uAlo[wbase + q * 2]     = *(uint32_t*)&pl0;
                uAlo[wbase + q * 2 + 1] = *(uint32_t*)&pl1;
            }
            __syncthreads();
        }

        // ---- mma main loop: K=64 in 4 k16 steps (conflict-free scalar LDS) --
        #pragma unroll
        for (int s = 0; s < 4; ++s) {
            uint32_t ah[4], al[4];
            int row = w * 16 + rIn;
            int wb = row * (SA_STRIDE / 2) + s * 8 + cgrp;
            const int R8 = 8 * (SA_STRIDE / 2);
            ah[0] = uAhi[wb];       ah[1] = uAhi[wb + R8];
            ah[2] = uAhi[wb + 4];   ah[3] = uAhi[wb + R8 + 4];
            al[0] = uAlo[wb];       al[1] = uAlo[wb + R8];
            al[2] = uAlo[wb + 4];   al[3] = uAlo[wb + R8 + 4];
            #pragma unroll
            for (int nt = 0; nt < 8; ++nt) {
                int n = nt * 8 + (lane >> 2);
                int bw = n * (SB_STRIDE / 2) + phase * 32 + s * 8 + cgrp;
                uint32_t bh[2] = { uBhi[bw], uBhi[bw + 4] };
                uint32_t bl[2] = { uBlo[bw], uBlo[bw + 4] };
                mma16816(acc[nt], ah, bh);
                mma16816(acc[nt], ah, bl);
                mma16816(acc[nt], al, bh);
            }
        }
    }

    // ---- epilogue -----------------------------------------------------------
    int r0 = base + w * 16 + rIn;
    int r1 = r0 + 8;
    if (do_fc) {
        float p0 = 0.f, p1 = 0.f;
        #pragma unroll
        for (int nt = 0; nt < 8; ++nt) {
            int ch = nt * 8 + 2 * cgrp;
            float w0 = Wfc[ch], w1 = Wfc[ch + 1];
            p0 += fmaxf(acc[nt][0], 0.f) * w0 + fmaxf(acc[nt][1], 0.f) * w1;
            p1 += fmaxf(acc[nt][2], 0.f) * w0 + fmaxf(acc[nt][3], 0.f) * w1;
        }
        p0 += __shfl_xor_sync(0xffffffffu, p0, 1);
        p0 += __shfl_xor_sync(0xffffffffu, p0, 2);
        p1 += __shfl_xor_sync(0xffffffffu, p1, 1);
        p1 += __shfl_xor_sync(0xffffffffu, p1, 2);
        if (cgrp == 0) {
            float bv = bfc[0];
            if (r0 < N_NODES) out[r0] = p0 + bv;
            if (r1 < N_NODES) out[r1] = p1 + bv;
        }
    } else {
        #pragma unroll
        for (int nt = 0; nt < 8; ++nt) {
            int ch = nt * 8 + 2 * cgrp;
            if (r0 < N_NODES) {
                float2 v = make_float2(fmaxf(acc[nt][0], 0.f),
                                       fmaxf(acc[nt][1], 0.f));
                *(float2*)(out + (long long)r0 * CH + ch) = v;
            }
            if (r1 < N_NODES) {
                float2 v = make_float2(fmaxf(acc[nt][2], 0.f),
                                       fmaxf(acc[nt][3], 0.f));
                *(float2*)(out + (long long)r1 * CH + ch) = v;
            }
        }
    }
}

// ---------------- launch -----------------------------------------------------
extern "C" void kernel_launch(void* const* d_in, const int* in_sizes, int n_in,
                              void* d_out, int out_size) {
    const float* x   = (const float*)d_in[0];
    const void*  ei  = d_in[1];
    const float* W1l = (const float*)d_in[2];
    const float* b1  = (const float*)d_in[3];
    const float* W1r = (const float*)d_in[4];
    const float* W2l = (const float*)d_in[5];
    const float* b2  = (const float*)d_in[6];
    const float* W2r = (const float*)d_in[7];
    const float* Wfc = (const float*)d_in[8];
    const float* bfc = (const float*)d_in[9];
    float* out = (float*)d_out;

    float* h1;
    cudaGetSymbolAddress((void**)&h1, g_h1);

    cudaFuncSetAttribute(dense_mma_kernel,
                         cudaFuncAttributeMaxDynamicSharedMemorySize, DENSE_SMEM);

    const int T = 256;
    int gridEdge  = (N_EDGES + T - 1) / T;
    int gridWarp  = (N_NODES * 32 + T - 1) / T;   // one warp per node
    int gridDense = (N_NODES + 127) / 128;

    count_kernel<<<gridEdge, T>>>(ei);
    scan_kernel<<<NB, SCAN_B>>>();
    fill_kernel<<<gridEdge, T>>>(ei);

    // layer 1 (gathers + stages directly from x; input is NaN-free)
    segmean_kernel<<<gridWarp, T>>>(x);
    dense_mma_kernel<<<gridDense, T, DENSE_SMEM>>>(x, W1l, W1r, b1,
                                                   Wfc, bfc, h1, 0);
    // layer 2 (+ fused fc head)
    segmean_kernel<<<gridWarp, T>>>(h1);
    dense_mma_kernel<<<gridDense, T, DENSE_SMEM>>>(h1, W2l, W2r, b2,
                                                   Wfc, bfc, out, 1);
}

// round 11
// speedup vs baseline: 1.2847x; 1.1046x over previous
#include <cuda_runtime.h>
#include <cuda_bf16.h>
#include <math.h>
#include <stdint.h>

#define N_NODES 100000
#define N_EDGES 1200000
#define CH 64
#define SCAN_B 1024
#define NB ((N_NODES + SCAN_B - 1) / SCAN_B)   // 98 blocks

// ---------------- scratch (static device memory; no allocs allowed) ----------
__device__ float          g_h1 [N_NODES * CH];
__device__ __nv_bfloat16  g_mhi[N_NODES * CH];   // mean, hi bf16 plane
__device__ __nv_bfloat16  g_mlo[N_NODES * CH];   // mean, lo bf16 plane
__device__ __nv_bfloat16  g_w1hi[64 * 128];      // layer1 [Wl|Wr] split, n-major
__device__ __nv_bfloat16  g_w1lo[64 * 128];
__device__ __nv_bfloat16  g_w2hi[64 * 128];
__device__ __nv_bfloat16  g_w2lo[64 * 128];
__device__ int   g_deg [N_NODES];        // zeroed at load; scan re-zeroes after use
__device__ int   g_rowstart[N_NODES + 1];
__device__ int   g_fill[N_NODES];
__device__ int   g_src_sorted[N_EDGES];
__device__ int   g_blk_stat[NB];         // 0 pending, 1 agg, 2 incl; fill resets
__device__ int   g_blk_agg[NB];
__device__ int   g_blk_inc[NB];

// ---------------- per-block edge dtype detection (warp ballot) ---------------
__device__ __forceinline__ int detect_is64_block(const void* ei, int* s_flag) {
    int tid = threadIdx.x;
    if (tid < 32) {
        const int* w = (const int*)ei;
        int ok = (w[2 * tid + 1] == 0) && (w[2 * (tid + 32) + 1] == 0);
        unsigned m = __ballot_sync(0xffffffffu, ok);
        if (tid == 0) *s_flag = (m == 0xffffffffu);
    }
    __syncthreads();
    return *s_flag;
}

__device__ __forceinline__ int load_idx(const void* ei, long long pos, int is64) {
    if (is64) return (int)((const long long*)ei)[pos];
    return ((const int*)ei)[pos];
}

// ---------------- split helper -----------------------------------------------
__device__ __forceinline__ void split_bf16(float v, __nv_bfloat16& hi, __nv_bfloat16& lo) {
    hi = __float2bfloat16_rn(v);
    lo = __float2bfloat16_rn(v - __bfloat162float(hi));
}

// ---------------- count degrees + (extra blocks) pre-split weights -----------
// Blocks [0, gridEdge): edge counting. Blocks [gridEdge, gridEdge+16): split
// the four 64x64 weight mats into bf16 hi/lo planes, [Wl|Wr] n-major x K128.
__global__ void count_kernel(const void* __restrict__ ei, int gridEdge,
                             const float* __restrict__ W1l, const float* __restrict__ W1r,
                             const float* __restrict__ W2l, const float* __restrict__ W2r) {
    if ((int)blockIdx.x >= gridEdge) {
        int t = (blockIdx.x - gridEdge) * blockDim.x + threadIdx.x;  // 0..4095
        int k = t >> 6, n = t & 63;
        __nv_bfloat16 hi, lo;
        split_bf16(W1l[t], hi, lo);
        g_w1hi[n * 128 + k] = hi;      g_w1lo[n * 128 + k] = lo;
        split_bf16(W1r[t], hi, lo);
        g_w1hi[n * 128 + 64 + k] = hi; g_w1lo[n * 128 + 64 + k] = lo;
        split_bf16(W2l[t], hi, lo);
        g_w2hi[n * 128 + k] = hi;      g_w2lo[n * 128 + k] = lo;
        split_bf16(W2r[t], hi, lo);
        g_w2hi[n * 128 + 64 + k] = hi; g_w2lo[n * 128 + 64 + k] = lo;
        return;
    }
    __shared__ int s_is64;
    int is64 = detect_is64_block(ei, &s_is64);
    int e = blockIdx.x * blockDim.x + threadIdx.x;
    if (e < N_EDGES) {
        int d = load_idx(ei, (long long)N_EDGES + e, is64);
        atomicAdd(&g_deg[d], 1);
    }
}

// ---------------- single-pass scan with decoupled lookback -------------------
__device__ __forceinline__ int block_incl_scan(int v, int* warp_sums) {
    int tid = threadIdx.x, lane = tid & 31, w = tid >> 5;
    int nw = blockDim.x >> 5;
    int incl = v;
    #pragma unroll
    for (int d = 1; d < 32; d <<= 1) {
        int t = __shfl_up_sync(0xffffffffu, incl, d);
        if (lane >= d) incl += t;
    }
    if (lane == 31) warp_sums[w] = incl;
    __syncthreads();
    if (w == 0) {
        int ws = (lane < nw) ? warp_sums[lane] : 0;
        #pragma unroll
        for (int d = 1; d < 32; d <<= 1) {
            int t = __shfl_up_sync(0xffffffffu, ws, d);
            if (lane >= d) ws += t;
        }
        if (lane < nw) warp_sums[lane] = ws;
    }
    __syncthreads();
    return incl + (w > 0 ? warp_sums[w - 1] : 0);
}

__global__ void __launch_bounds__(SCAN_B) scan_kernel() {
    __shared__ int warp_sums[32];
    __shared__ int s_excl;
    int b = blockIdx.x, tid = threadIdx.x;
    int i = b * SCAN_B + tid;
    int v = (i < N_NODES) ? g_deg[i] : 0;
    int incl = block_incl_scan(v, warp_sums);

    if (tid == SCAN_B - 1) {           // incl == block total here
        if (b == 0) {
            *((volatile int*)&g_blk_inc[0]) = incl;
            __threadfence();
            atomicExch(&g_blk_stat[0], 2);
        } else {
            *((volatile int*)&g_blk_agg[b]) = incl;
            __threadfence();
            atomicExch(&g_blk_stat[b], 1);
        }
    }
    if (tid == 0) {
        int excl = 0;
        if (b > 0) {
            int p = b - 1;
            while (true) {
                int s;
                do { s = atomicAdd(&g_blk_stat[p], 0); } while (s == 0);
                __threadfence();
                if (s == 2) { excl += *((volatile int*)&g_blk_inc[p]); break; }
                excl += *((volatile int*)&g_blk_agg[p]);
                --p;
            }
        }
        s_excl = excl;
    }
    __syncthreads();
    int excl = s_excl;
    if (tid == SCAN_B - 1 && b > 0) {
        *((volatile int*)&g_blk_inc[b]) = excl + incl;
        __threadfence();
        atomicExch(&g_blk_stat[b], 2);
    }
    if (i < N_NODES) {
        int ig = incl + excl;
        g_rowstart[i + 1] = ig;
        g_fill[i] = ig - v;
        g_deg[i] = 0;                  // self-restore for next launch
    }
    if (i == 0) g_rowstart[0] = 0;
}

// ---------------- fill CSR + reset scan flags --------------------------------
__global__ void fill_kernel(const void* __restrict__ ei) {
    __shared__ int s_is64;
    int is64 = detect_is64_block(ei, &s_is64);
    int e = blockIdx.x * blockDim.x + threadIdx.x;
    if (e < NB) g_blk_stat[e] = 0;
    if (e < N_EDGES) {
        int s = load_idx(ei, e, is64);
        int d = load_idx(ei, (long long)N_EDGES + e, is64);
        int pos = atomicAdd(&g_fill[d], 1);
        g_src_sorted[pos] = s;
    }
}

// ---------------- segment mean: one warp/node, writes split bf16 planes ------
__global__ void __launch_bounds__(256) segmean_kernel(const float* __restrict__ feat) {
    int node = (blockIdx.x * blockDim.x + threadIdx.x) >> 5;
    if (node >= N_NODES) return;
    int lane = threadIdx.x & 31;
    int beg = g_rowstart[node];
    int end = g_rowstart[node + 1];
    float ax = 0.f, ay = 0.f, bx = 0.f, by = 0.f;
    int e = beg;
    for (; e + 7 < end; e += 8) {
        int s0 = g_src_sorted[e];
        int s1 = g_src_sorted[e + 1];
        int s2 = g_src_sorted[e + 2];
        int s3 = g_src_sorted[e + 3];
        int s4 = g_src_sorted[e + 4];
        int s5 = g_src_sorted[e + 5];
        int s6 = g_src_sorted[e + 6];
        int s7 = g_src_sorted[e + 7];
        float2 v0 = ((const float2*)(feat + (long long)s0 * CH))[lane];
        float2 v1 = ((const float2*)(feat + (long long)s1 * CH))[lane];
        float2 v2 = ((const float2*)(feat + (long long)s2 * CH))[lane];
        float2 v3 = ((const float2*)(feat + (long long)s3 * CH))[lane];
        float2 v4 = ((const float2*)(feat + (long long)s4 * CH))[lane];
        float2 v5 = ((const float2*)(feat + (long long)s5 * CH))[lane];
        float2 v6 = ((const float2*)(feat + (long long)s6 * CH))[lane];
        float2 v7 = ((const float2*)(feat + (long long)s7 * CH))[lane];
        ax += v0.x; ay += v0.y;  bx += v1.x; by += v1.y;
        ax += v2.x; ay += v2.y;  bx += v3.x; by += v3.y;
        ax += v4.x; ay += v4.y;  bx += v5.x; by += v5.y;
        ax += v6.x; ay += v6.y;  bx += v7.x; by += v7.y;
    }
    for (; e + 3 < end; e += 4) {
        int s0 = g_src_sorted[e];
        int s1 = g_src_sorted[e + 1];
        int s2 = g_src_sorted[e + 2];
        int s3 = g_src_sorted[e + 3];
        float2 v0 = ((const float2*)(feat + (long long)s0 * CH))[lane];
        float2 v1 = ((const float2*)(feat + (long long)s1 * CH))[lane];
        float2 v2 = ((const float2*)(feat + (long long)s2 * CH))[lane];
        float2 v3 = ((const float2*)(feat + (long long)s3 * CH))[lane];
        ax += v0.x; ay += v0.y;  bx += v1.x; by += v1.y;
        ax += v2.x; ay += v2.y;  bx += v3.x; by += v3.y;
    }
    for (; e < end; ++e) {
        int s0 = g_src_sorted[e];
        float2 v0 = ((const float2*)(feat + (long long)s0 * CH))[lane];
        ax += v0.x; ay += v0.y;
    }
    ax += bx; ay += by;
    float inv = 1.0f / (float)max(end - beg, 1);
    ax *= inv; ay *= inv;
    __nv_bfloat16 h0, l0, h1, l1;
    split_bf16(ax, h0, l0); split_bf16(ay, h1, l1);
    __nv_bfloat162 ph; ph.x = h0; ph.y = h1;
    __nv_bfloat162 pl; pl.x = l0; pl.y = l1;
    ((uint32_t*)g_mhi)[node * 32 + lane] = *(uint32_t*)&ph;
    ((uint32_t*)g_mlo)[node * 32 + lane] = *(uint32_t*)&pl;
}

// ---------------- dense: split-bf16 MMA, weights & mean pre-split ------------
#define SA_STRIDE 72     // bf16 per A row -> 36 words
#define SB_STRIDE 136    // bf16 per B^T row -> 68 words
#define SA_ELEMS (128 * SA_STRIDE)
#define SB_ELEMS (64 * SB_STRIDE)
#define DENSE_SMEM ((2 * SA_ELEMS + 2 * SB_ELEMS) * 2)   // 71680 bytes

__device__ __forceinline__ void mma16816(float* c, const uint32_t* a, const uint32_t* b) {
    asm volatile(
        "mma.sync.aligned.m16n8k16.row.col.f32.bf16.bf16.f32 "
        "{%0,%1,%2,%3}, {%4,%5,%6,%7}, {%8,%9}, {%0,%1,%2,%3};"
        : "+f"(c[0]), "+f"(c[1]), "+f"(c[2]), "+f"(c[3])
        : "r"(a[0]), "r"(a[1]), "r"(a[2]), "r"(a[3]), "r"(b[0]), "r"(b[1]));
}

__global__ void __launch_bounds__(256) dense_mma_kernel(
    const float* __restrict__ root,
    const __nv_bfloat16* __restrict__ whi, const __nv_bfloat16* __restrict__ wlo,
    const float* __restrict__ bias,
    const float* __restrict__ Wfc, const float* __restrict__ bfc,
    float* __restrict__ out, int do_fc) {
    extern __shared__ __nv_bfloat16 smem[];
    __nv_bfloat16* sAhi = smem;
    __nv_bfloat16* sAlo = smem + SA_ELEMS;
    uint32_t* uAhi = (uint32_t*)sAhi;
    uint32_t* uAlo = (uint32_t*)sAlo;
    uint32_t* uBhi = (uint32_t*)(smem + 2 * SA_ELEMS);
    uint32_t* uBlo = (uint32_t*)(smem + 2 * SA_ELEMS + SB_ELEMS);

    int tid = threadIdx.x;
    int w = tid >> 5, lane = tid & 31;
    int base = blockIdx.x * 128;
    int cgrp = lane & 3;
    int rIn = lane >> 2;

    // ---- stage pre-split weights: pure uint4 copies, conflict-free STS.128 --
    {
        const uint4* gh = (const uint4*)whi;   // 64 rows x 16 uint4
        const uint4* gl = (const uint4*)wlo;
        #pragma unroll
        for (int i = tid; i < 64 * 16; i += 256) {
            int n = i >> 4, j = i & 15;
            *(uint4*)&uBhi[n * (SB_STRIDE / 2) + j * 4] = gh[i];
            *(uint4*)&uBlo[n * (SB_STRIDE / 2) + j * 4] = gl[i];
        }
    }

    // ---- stage A-mean: straight uint4 copies from pre-split planes ----------
    {
        int row = tid >> 1, half = tid & 1;
        int node = base + row;
        bool valid = node < N_NODES;
        const uint4* shi = (const uint4*)((const uint32_t*)g_mhi + (long long)node * 32) + half * 4;
        const uint4* slo = (const uint4*)((const uint32_t*)g_mlo + (long long)node * 32) + half * 4;
        int wb = row * (SA_STRIDE / 2) + half * 16;
        #pragma unroll
        for (int q = 0; q < 4; ++q) {
            uint4 vh = valid ? shi[q] : make_uint4(0, 0, 0, 0);
            uint4 vl = valid ? slo[q] : make_uint4(0, 0, 0, 0);
            *(uint4*)&uAhi[wb + q * 4] = vh;
            *(uint4*)&uAlo[wb + q * 4] = vl;
        }
    }

    // ---- bias into acc ------------------------------------------------------
    float acc[8][4];
    #pragma unroll
    for (int nt = 0; nt < 8; ++nt) {
        int ch = nt * 8 + 2 * cgrp;
        float bv0 = bias[ch], bv1 = bias[ch + 1];
        acc[nt][0] = bv0; acc[nt][1] = bv1;
        acc[nt][2] = bv0; acc[nt][3] = bv1;
    }

    __syncthreads();

    #pragma unroll
    for (int phase = 0; phase < 2; ++phase) {
        if (phase == 1) {
            __syncthreads();   // phase-0 readers done before overwrite
            // stage root features fp32 -> split: thread t -> row t>>1, half t&1
            int row = tid >> 1, half = tid & 1;
            int node = base + row;
            bool valid = node < N_NODES;
            const float4* src = (const float4*)(root + (long long)node * CH) + half * 8;
            int wbase = row * (SA_STRIDE / 2) + half * 16;
            #pragma unroll
            for (int q = 0; q < 8; ++q) {
                float4 v = valid ? src[q] : make_float4(0.f, 0.f, 0.f, 0.f);
                __nv_bfloat16 h0, l0, h1, l1, h2, l2, h3, l3;
                split_bf16(v.x, h0, l0); split_bf16(v.y, h1, l1);
                split_bf16(v.z, h2, l2); split_bf16(v.w, h3, l3);
                __nv_bfloat162 ph0; ph0.x = h0; ph0.y = h1;
                __nv_bfloat162 ph1; ph1.x = h2; ph1.y = h3;
                __nv_bfloat162 pl0; pl0.x = l0; pl0.y = l1;
                __nv_bfloat162 pl1; pl1.x = l2; pl1.y = l3;
                uAhi[wbase + q * 2]     = *(uint32_t*)&ph0;
                uAhi[wbase + q * 2 + 1] = *(uint32_t*)&ph1;
                uAlo[wbase + q * 2]     = *(uint32_t*)&pl0;
                uAlo[wbase + q * 2 + 1] = *(uint32_t*)&pl1;
            }
            __syncthreads();
        }

        // ---- mma main loop: K=64 in 4 k16 steps (conflict-free scalar LDS) --
        #pragma unroll
        for (int s = 0; s < 4; ++s) {
            uint32_t ah[4], al[4];
            int row = w * 16 + rIn;
            int wb = row * (SA_STRIDE / 2) + s * 8 + cgrp;
            const int R8 = 8 * (SA_STRIDE / 2);
            ah[0] = uAhi[wb];       ah[1] = uAhi[wb + R8];
            ah[2] = uAhi[wb + 4];   ah[3] = uAhi[wb + R8 + 4];
            al[0] = uAlo[wb];       al[1] = uAlo[wb + R8];
            al[2] = uAlo[wb + 4];   al[3] = uAlo[wb + R8 + 4];
            #pragma unroll
            for (int nt = 0; nt < 8; ++nt) {
                int n = nt * 8 + (lane >> 2);
                int bw = n * (SB_STRIDE / 2) + phase * 32 + s * 8 + cgrp;
                uint32_t bh[2] = { uBhi[bw], uBhi[bw + 4] };
                uint32_t bl[2] = { uBlo[bw], uBlo[bw + 4] };
                mma16816(acc[nt], ah, bh);
                mma16816(acc[nt], ah, bl);
                mma16816(acc[nt], al, bh);
            }
        }
    }

    // ---- epilogue -----------------------------------------------------------
    int r0 = base + w * 16 + rIn;
    int r1 = r0 + 8;
    if (do_fc) {
        float p0 = 0.f, p1 = 0.f;
        #pragma unroll
        for (int nt = 0; nt < 8; ++nt) {
            int ch = nt * 8 + 2 * cgrp;
            float w0 = Wfc[ch], w1 = Wfc[ch + 1];
            p0 += fmaxf(acc[nt][0], 0.f) * w0 + fmaxf(acc[nt][1], 0.f) * w1;
            p1 += fmaxf(acc[nt][2], 0.f) * w0 + fmaxf(acc[nt][3], 0.f) * w1;
        }
        p0 += __shfl_xor_sync(0xffffffffu, p0, 1);
        p0 += __shfl_xor_sync(0xffffffffu, p0, 2);
        p1 += __shfl_xor_sync(0xffffffffu, p1, 1);
        p1 += __shfl_xor_sync(0xffffffffu, p1, 2);
        if (cgrp == 0) {
            float bv = bfc[0];
            if (r0 < N_NODES) out[r0] = p0 + bv;
            if (r1 < N_NODES) out[r1] = p1 + bv;
        }
    } else {
        #pragma unroll
        for (int nt = 0; nt < 8; ++nt) {
            int ch = nt * 8 + 2 * cgrp;
            if (r0 < N_NODES) {
                float2 v = make_float2(fmaxf(acc[nt][0], 0.f),
                                       fmaxf(acc[nt][1], 0.f));
                *(float2*)(out + (long long)r0 * CH + ch) = v;
            }
            if (r1 < N_NODES) {
                float2 v = make_float2(fmaxf(acc[nt][2], 0.f),
                                       fmaxf(acc[nt][3], 0.f));
                *(float2*)(out + (long long)r1 * CH + ch) = v;
            }
        }
    }
}

// ---------------- launch -----------------------------------------------------
extern "C" void kernel_launch(void* const* d_in, const int* in_sizes, int n_in,
                              void* d_out, int out_size) {
    const float* x   = (const float*)d_in[0];
    const void*  ei  = d_in[1];
    const float* W1l = (const float*)d_in[2];
    const float* b1  = (const float*)d_in[3];
    const float* W1r = (const float*)d_in[4];
    const float* W2l = (const float*)d_in[5];
    const float* b2  = (const float*)d_in[6];
    const float* W2r = (const float*)d_in[7];
    const float* Wfc = (const float*)d_in[8];
    const float* bfc = (const float*)d_in[9];
    float* out = (float*)d_out;

    float* h1;
    __nv_bfloat16 *w1hi, *w1lo, *w2hi, *w2lo;
    cudaGetSymbolAddress((void**)&h1,   g_h1);
    cudaGetSymbolAddress((void**)&w1hi, g_w1hi);
    cudaGetSymbolAddress((void**)&w1lo, g_w1lo);
    cudaGetSymbolAddress((void**)&w2hi, g_w2hi);
    cudaGetSymbolAddress((void**)&w2lo, g_w2lo);

    cudaFuncSetAttribute(dense_mma_kernel,
                         cudaFuncAttributeMaxDynamicSharedMemorySize, DENSE_SMEM);

    const int T = 256;
    int gridEdge  = (N_EDGES + T - 1) / T;
    int gridWarp  = (N_NODES * 32 + T - 1) / T;   // one warp per node
    int gridDense = (N_NODES + 127) / 128;

    count_kernel<<<gridEdge + 16, T>>>(ei, gridEdge, W1l, W1r, W2l, W2r);
    scan_kernel<<<NB, SCAN_B>>>();
    fill_kernel<<<gridEdge, T>>>(ei);

    // layer 1 (gathers + stages directly from x; input is NaN-free)
    segmean_kernel<<<gridWarp, T>>>(x);
    dense_mma_kernel<<<gridDense, T, DENSE_SMEM>>>(x, w1hi, w1lo, b1,
                                                   Wfc, bfc, h1, 0);
    // layer 2 (+ fused fc head)
    segmean_kernel<<<gridWarp, T>>>(h1);
    dense_mma_kernel<<<gridDense, T, DENSE_SMEM>>>(h1, w2hi, w2lo, b2,
                                                   Wfc, bfc, out, 1);
}